// round 16
// baseline (speedup 1.0000x reference)
#include <cuda_runtime.h>
#include <cuda_fp16.h>
#include <math.h>
#include <stdint.h>

#define B_   16
#define T_   1024
#define D_   512
#define H_   8
#define DH   64
#define FFN_ 2048
#define SEH  256
#define ROWS (B_*T_)   // 16384

// ---------------- scratch (static device allocations) ---------------------------
__device__ __align__(16) float g_y[ROWS];
__device__ __align__(16) float g_z1[B_*SEH];
__device__ __align__(16) float g_gate[ROWS];
__device__ __align__(16) __half g_qkvh[3*ROWS*D_];   // q(/8),k,v fp16
__device__ __align__(16) __half g_nhi[ROWS*D_];
__device__ __align__(16) __half g_hhi[ROWS*FFN_];
__device__ __align__(16) __half g_wqkvT[3*D_*D_];
__device__ __align__(16) __half g_w1T[FFN_*D_];
__device__ __align__(16) __half g_w2T[D_*FFN_];

// ---------------- helpers -------------------------------------------------------
#define SWZ(o) ((o) ^ (((o) >> 3) & 0x70))

__device__ __forceinline__ uint32_t smem_u32(const void* p) {
    uint32_t a;
    asm("{ .reg .u64 t; cvta.to.shared.u64 t, %1; cvt.u32.u64 %0, t; }" : "=r"(a) : "l"(p));
    return a;
}
__device__ __forceinline__ void cp16(uint32_t dst, const void* src) {
    asm volatile("cp.async.cg.shared.global [%0], [%1], 16;" :: "r"(dst), "l"(src) : "memory");
}
__device__ __forceinline__ void ldsm4(uint32_t* r, uint32_t a) {
    asm volatile("ldmatrix.sync.aligned.m8n8.x4.shared.b16 {%0,%1,%2,%3}, [%4];"
                 : "=r"(r[0]), "=r"(r[1]), "=r"(r[2]), "=r"(r[3]) : "r"(a));
}
__device__ __forceinline__ void ldsm4t(uint32_t* r, uint32_t a) {
    asm volatile("ldmatrix.sync.aligned.m8n8.x4.trans.shared.b16 {%0,%1,%2,%3}, [%4];"
                 : "=r"(r[0]), "=r"(r[1]), "=r"(r[2]), "=r"(r[3]) : "r"(a));
}
__device__ __forceinline__ void mma16816(float* d, const uint32_t* a, uint32_t b0, uint32_t b1) {
    asm volatile(
        "mma.sync.aligned.m16n8k16.row.col.f32.f16.f16.f32 "
        "{%0,%1,%2,%3}, {%4,%5,%6,%7}, {%8,%9}, {%0,%1,%2,%3};"
        : "+f"(d[0]), "+f"(d[1]), "+f"(d[2]), "+f"(d[3])
        : "r"(a[0]), "r"(a[1]), "r"(a[2]), "r"(a[3]), "r"(b0), "r"(b1));
}
__device__ __forceinline__ float gelu_f(float x) {
    return 0.5f * x * (1.0f + erff(x * 0.70710678118654752f));
}

// ---------------- row means (prologue) ------------------------------------------
__global__ __launch_bounds__(256) void rowmean_k(const float* __restrict__ x) {
    const int row  = blockIdx.x * 8 + (threadIdx.x >> 5);
    const int lane = threadIdx.x & 31;
    const float4* xr = (const float4*)(x + (size_t)row * D_);
    float s = 0.f;
#pragma unroll
    for (int i = 0; i < 4; i++) {
        float4 v = xr[lane + 32 * i];
        s += v.x + v.y + v.z + v.w;
    }
#pragma unroll
    for (int off = 16; off >= 1; off >>= 1) s += __shfl_xor_sync(0xffffffffu, s, off);
    if (lane == 0) g_y[row] = s * (1.f / D_);
}

// ---------------- fused SE fc1 + weight transposes ------------------------------
__global__ __launch_bounds__(256) void se_fc1_prep_k(
    const float* __restrict__ se_w1,
    const float* __restrict__ wq, const float* __restrict__ wk,
    const float* __restrict__ wv, const float* __restrict__ w1,
    const float* __restrict__ w2) {
    __shared__ float smf[1280];
    const int id = blockIdx.x;
    const int tid = threadIdx.x;
    if (id < 256) {
        float* ys = smf;
        float* ps = smf + 1024;
        const int b = id & 15, jt = id >> 4;
        for (int i = tid; i < T_; i += 256) ys[i] = g_y[b * T_ + i];
        __syncthreads();
        const int j = jt * 16 + (tid & 15);
        const int ks = tid >> 4;
        float acc = 0.f;
        const float* wp = se_w1 + (size_t)(ks * 64) * SEH + j;
        const float* yp = ys + ks * 64;
#pragma unroll 8
        for (int i = 0; i < 64; i++) acc += yp[i] * wp[(size_t)i * SEH];
        ps[tid] = acc;
        __syncthreads();
        if (tid < 16) {
            float s = ps[tid];
#pragma unroll
            for (int r = 1; r < 16; r++) s += ps[tid + r * 16];
            g_z1[b * SEH + jt * 16 + tid] = fmaxf(s, 0.f);
        }
        return;
    }
    float (*ts)[33] = (float(*)[33])smf;
    const int id2 = id - 256;
    const float* W;
    __half* Thi;
    int K, N, kb, nb;
    if (id2 < 768) {
        const int which = id2 >> 8, t = id2 & 255;
        W = (which == 0) ? wq : (which == 1) ? wk : wv;
        Thi = g_wqkvT + which * D_ * D_;
        K = D_; N = D_;
        nb = (t & 15) * 32; kb = (t >> 4) * 32;
    } else if (id2 < 1792) {
        const int t = id2 - 768;
        W = w1; Thi = g_w1T;
        K = D_; N = FFN_;
        nb = (t & 63) * 32; kb = (t >> 6) * 32;
    } else {
        const int t = id2 - 1792;
        W = w2; Thi = g_w2T;
        K = FFN_; N = D_;
        nb = (t & 15) * 32; kb = (t >> 4) * 32;
    }
    const int tx = tid & 31, ty = tid >> 5;
#pragma unroll
    for (int i = 0; i < 32; i += 8)
        ts[ty + i][tx] = W[(size_t)(kb + ty + i) * N + nb + tx];
    __syncthreads();
#pragma unroll
    for (int i = 0; i < 32; i += 8) {
        float v = ts[tx][ty + i];
        Thi[(size_t)(nb + ty + i) * K + kb + tx] = __float2half_rn(v);
    }
}

// ---------------- fused SE fc2 + gated LayerNorm -> fp16 ------------------------
__global__ __launch_bounds__(256) void se_fc2_ln_k(
    const float* __restrict__ w2, const float* __restrict__ x,
    const float* __restrict__ gw, const float* __restrict__ bw) {
    __shared__ float zs[SEH];
    __shared__ float ps[256];
    __shared__ float gs[64];
    const int b = blockIdx.x, tt = blockIdx.y;
    const int tid = threadIdx.x;
    if (tid < SEH) zs[tid] = g_z1[b * SEH + tid];
    __syncthreads();
    const int t = tt * 64 + (tid & 63);
    const int ks = tid >> 6;
    float acc = 0.f;
    const float* wp = w2 + (size_t)(ks * 64) * T_ + t;
    const float* zp = zs + ks * 64;
#pragma unroll 8
    for (int j = 0; j < 64; j++) acc += zp[j] * wp[(size_t)j * T_];
    ps[tid] = acc;
    __syncthreads();
    if (tid < 64) {
        float s = ps[tid] + ps[tid + 64] + ps[tid + 128] + ps[tid + 192];
        float g = 1.f / (1.f + __expf(-s));
        g_gate[b * T_ + tt * 64 + tid] = g;
        gs[tid] = g;
    }
    __syncthreads();

    const int wrp = tid >> 5, lane = tid & 31;
    for (int rr = wrp; rr < 64; rr += 8) {
        const int row = b * T_ + tt * 64 + rr;
        const float gm = 1.f + gs[rr];
        const float4* xr = (const float4*)(x + (size_t)row * D_);
        float4 r[4];
        float s = 0.f, s2 = 0.f;
#pragma unroll
        for (int i = 0; i < 4; i++) {
            float4 v = xr[lane + 32 * i];
            v.x *= gm; v.y *= gm; v.z *= gm; v.w *= gm;
            r[i] = v;
            s  += v.x + v.y + v.z + v.w;
            s2 += v.x * v.x + v.y * v.y + v.z * v.z + v.w * v.w;
        }
#pragma unroll
        for (int off = 16; off >= 1; off >>= 1) {
            s  += __shfl_xor_sync(0xffffffffu, s, off);
            s2 += __shfl_xor_sync(0xffffffffu, s2, off);
        }
        float mu = s * (1.f / D_);
        float rs = rsqrtf(s2 * (1.f / D_) - mu * mu + 1e-5f);
        const float4* g4 = (const float4*)gw;
        const float4* b4 = (const float4*)bw;
        uint2* hrow = (uint2*)(g_nhi + (size_t)row * D_);
#pragma unroll
        for (int i = 0; i < 4; i++) {
            int c = lane + 32 * i;
            float4 g = g4[c], bb = b4[c], v = r[i];
            v.x = (v.x - mu) * rs * g.x + bb.x;
            v.y = (v.y - mu) * rs * g.y + bb.y;
            v.z = (v.z - mu) * rs * g.z + bb.z;
            v.w = (v.w - mu) * rs * g.w + bb.w;
            __half2 h01 = __floats2half2_rn(v.x, v.y);
            __half2 h23 = __floats2half2_rn(v.z, v.w);
            uint2 hw;
            hw.x = *(uint32_t*)&h01; hw.y = *(uint32_t*)&h23;
            hrow[c] = hw;
        }
    }
}

// ---------------- plain LayerNorm -> fp16 (FFN pre-norm; 8 rows/CTA) -------------
__global__ __launch_bounds__(256) void ln_split_k(
    const float* __restrict__ x, const float* __restrict__ gw,
    const float* __restrict__ bw) {
    int row  = blockIdx.x * 8 + (threadIdx.x >> 5);
    int lane = threadIdx.x & 31;
    const float4* xr = (const float4*)(x + (size_t)row * D_);
    float4 r[4];
    float s = 0.f, s2 = 0.f;
#pragma unroll
    for (int i = 0; i < 4; i++) {
        float4 v = xr[lane + 32 * i];
        r[i] = v;
        s  += v.x + v.y + v.z + v.w;
        s2 += v.x * v.x + v.y * v.y + v.z * v.z + v.w * v.w;
    }
#pragma unroll
    for (int off = 16; off >= 1; off >>= 1) {
        s  += __shfl_xor_sync(0xffffffffu, s, off);
        s2 += __shfl_xor_sync(0xffffffffu, s2, off);
    }
    float mu = s * (1.f / D_);
    float rs = rsqrtf(s2 * (1.f / D_) - mu * mu + 1e-5f);
    const float4* g4 = (const float4*)gw;
    const float4* b4 = (const float4*)bw;
    uint2* hrow = (uint2*)(g_nhi + (size_t)row * D_);
#pragma unroll
    for (int i = 0; i < 4; i++) {
        int c = lane + 32 * i;
        float4 g = g4[c], bb = b4[c], v = r[i];
        v.x = (v.x - mu) * rs * g.x + bb.x;
        v.y = (v.y - mu) * rs * g.y + bb.y;
        v.z = (v.z - mu) * rs * g.z + bb.z;
        v.w = (v.w - mu) * rs * g.w + bb.w;
        __half2 h01 = __floats2half2_rn(v.x, v.y);
        __half2 h23 = __floats2half2_rn(v.z, v.w);
        uint2 hw;
        hw.x = *(uint32_t*)&h01; hw.y = *(uint32_t*)&h23;
        hrow[c] = hw;
    }
}

// ---------------- single-pass fp16 HMMA GEMM ------------------------------------
// Tile AM = MTP*32 (MTP m-fragments per warp, warp tile (MTP*16) x 64), BN = 256.
// MTP=1 + MINB=3: small tile, 3 CTAs/SM (kills wave quantization on QKV).
// MTP=2 + MINB=2: standard 64x256 tile.
#define BTILE 32768              // 256 rows x 128B

template <int EPI, int MTP, int MINB>
__global__ __launch_bounds__(256, MINB)
void gemm_mma(const __half* __restrict__ Ahi, const __half* __restrict__ Bhi,
              const float* __restrict__ bias, const float* __restrict__ res,
              float* __restrict__ Cf, __half* __restrict__ Chi,
              int K, int ldc) {
    constexpr int AM    = MTP * 32;
    constexpr int ATILE = AM * 128;
    constexpr int GSTG  = ATILE + BTILE;
    extern __shared__ char smem[];
    const uint32_t sbase = smem_u32(smem);
    const int tid = threadIdx.x;
    const int bm = blockIdx.y * AM, bn = blockIdx.x * 256;
    const int wid = tid >> 5, lane = tid & 31;
    const int wm = wid >> 2, wn = wid & 3;   // warp tile (MTP*16)m x 64n

    float acc[MTP][8][4];
#pragma unroll
    for (int i = 0; i < MTP; i++)
#pragma unroll
        for (int j = 0; j < 8; j++)
#pragma unroll
            for (int f = 0; f < 4; f++) acc[i][j][f] = 0.f;

    const int NC = K >> 6;
    const int lrow = (lane & 7) + ((lane >> 3) & 1) * 8;
    const int lch  = lane >> 4;

    uint32_t arow[MTP], brow[4];
#pragma unroll
    for (int mt = 0; mt < MTP; mt++) arow[mt] = (wm * (MTP * 16) + mt * 16 + lrow) * 128;
#pragma unroll
    for (int nb = 0; nb < 4; nb++) brow[nb] = (wn * 64 + nb * 16 + lrow) * 128;

#define LOAD_CHUNK(c)                                                              \
    {                                                                              \
        const uint32_t stg = sbase + ((c) & 1) * GSTG;                             \
        const int kc = (c) << 6;                                                   \
        _Pragma("unroll")                                                          \
        for (int i = 0; i < MTP; i++) {                                            \
            int slot = tid + i * 256;                                              \
            int r = slot >> 3, ch = slot & 7;                                      \
            cp16(stg + SWZ(r * 128 + ch * 16),                                     \
                 Ahi + (size_t)(bm + r) * K + kc + ch * 8);                        \
        }                                                                          \
        _Pragma("unroll")                                                          \
        for (int i = 0; i < 8; i++) {                                              \
            int slot = tid + i * 256;                                              \
            int r = slot >> 3, ch = slot & 7;                                      \
            cp16(stg + ATILE + SWZ(r * 128 + ch * 16),                             \
                 Bhi + (size_t)(bn + r) * K + kc + ch * 8);                        \
        }                                                                          \
        asm volatile("cp.async.commit_group;" ::: "memory");                       \
    }

    LOAD_CHUNK(0);
    for (int c = 0; c < NC; c++) {
        if (c + 1 < NC) {
            LOAD_CHUNK(c + 1);
            asm volatile("cp.async.wait_group 1;" ::: "memory");
        } else {
            asm volatile("cp.async.wait_group 0;" ::: "memory");
        }
        __syncthreads();
        const uint32_t stg = sbase + (c & 1) * GSTG;
#pragma unroll
        for (int k16 = 0; k16 < 4; k16++) {
            const uint32_t cb = (k16 * 2 + lch) * 16;
            uint32_t ah[MTP][4], bh[4][4];
#pragma unroll
            for (int mt = 0; mt < MTP; mt++) ldsm4(ah[mt], stg + SWZ(arow[mt] + cb));
#pragma unroll
            for (int nb = 0; nb < 4; nb++) ldsm4(bh[nb], stg + ATILE + SWZ(brow[nb] + cb));
#pragma unroll
            for (int mt = 0; mt < MTP; mt++)
#pragma unroll
                for (int nb = 0; nb < 4; nb++)
#pragma unroll
                    for (int hf = 0; hf < 2; hf++)
                        mma16816(acc[mt][nb * 2 + hf], ah[mt], bh[nb][hf], bh[nb][hf + 2]);
        }
        __syncthreads();
    }

    const int er = bm + wm * (MTP * 16) + (lane >> 2);
    const int ec = bn + wn * 64 + (lane & 3) * 2;
#pragma unroll
    for (int mt = 0; mt < MTP; mt++)
#pragma unroll
        for (int rr = 0; rr < 2; rr++) {
            const int row = er + mt * 16 + rr * 8;
#pragma unroll
            for (int nf = 0; nf < 8; nf++) {
                const int col = ec + nf * 8;
                float v0 = acc[mt][nf][rr * 2 + 0];
                float v1 = acc[mt][nf][rr * 2 + 1];
                if (EPI == 0) {
                    const int buf = col >> 9;
                    const float sc = (buf == 0) ? 0.125f : 1.f;
                    v0 *= sc; v1 *= sc;
                    __half2 h = __floats2half2_rn(v0, v1);
                    size_t a = ((size_t)buf * ROWS + row) * 512 + (col & 511);
                    *(__half2*)(Chi + a) = h;
                } else if (EPI == 1) {
                    v0 = gelu_f(v0 + bias[col]);
                    v1 = gelu_f(v1 + bias[col + 1]);
                    __half2 h = __floats2half2_rn(v0, v1);
                    *(__half2*)(Chi + (size_t)row * ldc + col) = h;
                } else {
                    const float2 rr2 = *(const float2*)(res + (size_t)row * ldc + col);
                    float2 o = make_float2(v0 + bias[col] + rr2.x, v1 + bias[col + 1] + rr2.y);
                    *(float2*)(Cf + (size_t)row * ldc + col) = o;
                }
            }
        }
}

// ---------------- fp16 HMMA flash attention, max-free softmax -------------------
#define ASMEM (16384 + 2 * 16384)

__global__ __launch_bounds__(256, 2)
void attn_mma(const __half* __restrict__ qkvh,
              const float* __restrict__ x, float* __restrict__ out) {
    extern __shared__ char smem[];
    const uint32_t sbase = smem_u32(smem);
    const int b = blockIdx.z, h = blockIdx.y, qt = blockIdx.x;
    const int tid = threadIdx.x, w = tid >> 5, lane = tid & 31;
    const int bq = b * T_ + qt * 128;
    const int bk0 = b * T_;
    const int lrow = (lane & 7) + ((lane >> 3) & 1) * 8;
    const int lch  = lane >> 4;

    const __half* kh = qkvh + (size_t)ROWS * D_;
    const __half* vh = qkvh + 2 * (size_t)ROWS * D_;

    {
#pragma unroll
        for (int i = 0; i < 4; i++) {
            int slot = tid + i * 256;
            int r = slot >> 3, ch = slot & 7;
            cp16(sbase + SWZ(r * 128 + ch * 16),
                 qkvh + (size_t)(bq + r) * D_ + h * DH + ch * 8);
        }
    }
#define LOAD_KV(kt)                                                                \
    {                                                                              \
        const uint32_t stg = sbase + 16384 + ((kt) & 1) * 16384;                   \
        const int bk = bk0 + (kt) * 64;                                            \
        _Pragma("unroll")                                                          \
        for (int i = 0; i < 2; i++) {                                              \
            int slot = tid + i * 256;                                              \
            int r = slot >> 3, ch = slot & 7;                                      \
            cp16(stg + SWZ(r * 128 + ch * 16),                                     \
                 kh + (size_t)(bk + r) * D_ + h * DH + ch * 8);                    \
            cp16(stg + 8192 + SWZ(r * 128 + ch * 16),                              \
                 vh + (size_t)(bk + r) * D_ + h * DH + ch * 8);                    \
        }                                                                          \
        asm volatile("cp.async.commit_group;" ::: "memory");                       \
    }
    LOAD_KV(0);

    uint32_t qfh[4][4];
    float oacc[8][4];
#pragma unroll
    for (int t = 0; t < 8; t++)
#pragma unroll
        for (int f = 0; f < 4; f++) oacc[t][f] = 0.f;
    float l0 = 0.f, l1 = 0.f;

    for (int kt = 0; kt < 16; kt++) {
        if (kt + 1 < 16) {
            LOAD_KV(kt + 1);
            asm volatile("cp.async.wait_group 1;" ::: "memory");
        } else {
            asm volatile("cp.async.wait_group 0;" ::: "memory");
        }
        __syncthreads();

        if (kt == 0) {
#pragma unroll
            for (int j = 0; j < 4; j++)
                ldsm4(qfh[j], sbase + SWZ((w * 16 + lrow) * 128 + (j * 2 + lch) * 16));
        }
        const uint32_t stg = sbase + 16384 + (kt & 1) * 16384;

        // ---- S = Q K^T ----
        float sacc[8][4];
#pragma unroll
        for (int t = 0; t < 8; t++)
#pragma unroll
            for (int f = 0; f < 4; f++) sacc[t][f] = 0.f;
#pragma unroll
        for (int k16 = 0; k16 < 4; k16++) {
            const uint32_t cb = (k16 * 2 + lch) * 16;
            uint32_t bh[4][4];
#pragma unroll
            for (int g = 0; g < 4; g++)
                ldsm4(bh[g], stg + SWZ((g * 16 + lrow) * 128 + cb));
#pragma unroll
            for (int g = 0; g < 4; g++)
#pragma unroll
                for (int hf = 0; hf < 2; hf++)
                    mma16816(sacc[2 * g + hf], qfh[k16], bh[g][hf], bh[g][hf + 2]);
        }

        // ---- P = exp(S); per-thread l; convert to fragments ----
        uint32_t pa[4][4];
#pragma unroll
        for (int k16 = 0; k16 < 4; k16++)
#pragma unroll
            for (int half = 0; half < 2; half++) {
                const float* t0 = sacc[2 * k16 + half];
                float e0 = __expf(t0[0]);
                float e1 = __expf(t0[1]);
                float e2 = __expf(t0[2]);
                float e3 = __expf(t0[3]);
                l0 += e0 + e1;
                l1 += e2 + e3;
                __half2 h0 = __floats2half2_rn(e0, e1);
                __half2 h1 = __floats2half2_rn(e2, e3);
                pa[k16][2 * half + 0] = *(uint32_t*)&h0;
                pa[k16][2 * half + 1] = *(uint32_t*)&h1;
            }

        // ---- O += P V ----
        const uint32_t vs = stg + 8192;
        const int vr = (lane & 7) + ((lane >> 4) << 3);
        const int vb = ((lane >> 3) & 1) * 16;
#pragma unroll
        for (int k16 = 0; k16 < 4; k16++) {
#pragma unroll
            for (int nb = 0; nb < 4; nb++) {
                const uint32_t off = SWZ((k16 * 16 + vr) * 128 + nb * 32 + vb);
                uint32_t fvh[4];
                ldsm4t(fvh, vs + off);
#pragma unroll
                for (int hf = 0; hf < 2; hf++)
                    mma16816(oacc[2 * nb + hf], pa[k16], fvh[hf], fvh[hf + 2]);
            }
        }
        __syncthreads();
    }

    // ---- epilogue: row-sum reduce, then out = x*(1+gate) + O/l ----
    l0 += __shfl_xor_sync(0xffffffffu, l0, 1);
    l0 += __shfl_xor_sync(0xffffffffu, l0, 2);
    l1 += __shfl_xor_sync(0xffffffffu, l1, 1);
    l1 += __shfl_xor_sync(0xffffffffu, l1, 2);
    const float i0 = 1.f / l0, i1 = 1.f / l1;
    const int r0 = bq + w * 16 + (lane >> 2);
    const float gm0 = 1.f + g_gate[r0];
    const float gm1 = 1.f + g_gate[r0 + 8];
    const int cbase = h * DH + 2 * (lane & 3);
#pragma unroll
    for (int dt = 0; dt < 8; dt++) {
        const int col = cbase + dt * 8;
        const float2 x0 = *(const float2*)(x + (size_t)r0 * D_ + col);
        const float2 x1 = *(const float2*)(x + (size_t)(r0 + 8) * D_ + col);
        float2 o0 = make_float2(x0.x * gm0 + oacc[dt][0] * i0, x0.y * gm0 + oacc[dt][1] * i0);
        float2 o1 = make_float2(x1.x * gm1 + oacc[dt][2] * i1, x1.y * gm1 + oacc[dt][3] * i1);
        *(float2*)(out + (size_t)r0 * D_ + col) = o0;
        *(float2*)(out + (size_t)(r0 + 8) * D_ + col) = o1;
    }
}

// ---------------- launch --------------------------------------------------------
extern "C" void kernel_launch(void* const* d_in, const int* in_sizes, int n_in,
                              void* d_out, int out_size) {
    const float* x     = (const float*)d_in[0];
    const float* wq    = (const float*)d_in[1];
    const float* wk    = (const float*)d_in[2];
    const float* wv    = (const float*)d_in[3];
    const float* ln1_g = (const float*)d_in[4];
    const float* ln1_b = (const float*)d_in[5];
    const float* se_w1 = (const float*)d_in[6];
    const float* se_w2 = (const float*)d_in[7];
    const float* ffn_g = (const float*)d_in[8];
    const float* ffn_b = (const float*)d_in[9];
    const float* w1    = (const float*)d_in[10];
    const float* b1    = (const float*)d_in[11];
    const float* w2    = (const float*)d_in[12];
    const float* b2    = (const float*)d_in[13];
    float* out = (float*)d_out;

    __half *qkvh, *nhi, *hhi, *wqkvT, *w1T, *w2T;
    cudaGetSymbolAddress((void**)&qkvh,  g_qkvh);
    cudaGetSymbolAddress((void**)&nhi,   g_nhi);
    cudaGetSymbolAddress((void**)&hhi,   g_hhi);
    cudaGetSymbolAddress((void**)&wqkvT, g_wqkvT);
    cudaGetSymbolAddress((void**)&w1T,   g_w1T);
    cudaGetSymbolAddress((void**)&w2T,   g_w2T);

    const int GS1 = 2 * (32 * 128 + BTILE);   // MTP=1: 73728
    const int GS2 = 2 * (64 * 128 + BTILE);   // MTP=2: 81920
    cudaFuncSetAttribute(attn_mma, cudaFuncAttributeMaxDynamicSharedMemorySize, ASMEM);
    cudaFuncSetAttribute((const void*)gemm_mma<0, 1, 3>,
                         cudaFuncAttributeMaxDynamicSharedMemorySize, GS1);
    cudaFuncSetAttribute((const void*)gemm_mma<1, 2, 2>,
                         cudaFuncAttributeMaxDynamicSharedMemorySize, GS2);
    cudaFuncSetAttribute((const void*)gemm_mma<2, 2, 2>,
                         cudaFuncAttributeMaxDynamicSharedMemorySize, GS2);

    rowmean_k<<<ROWS / 8, 256>>>(x);
    se_fc1_prep_k<<<256 + 2816, 256>>>(se_w1, wq, wk, wv, w1, w2);
    se_fc2_ln_k<<<dim3(B_, 16), 256>>>(se_w2, x, ln1_g, ln1_b);
    gemm_mma<0, 1, 3><<<dim3(6, 512), 256, GS1>>>(nhi, wqkvT, nullptr, nullptr,
                                                  nullptr, qkvh, D_, 512);
    attn_mma<<<dim3(T_ / 128, H_, B_), 256, ASMEM>>>(qkvh, x, out);

    ln_split_k<<<ROWS / 8, 256>>>(out, ffn_g, ffn_b);
    gemm_mma<1, 2, 2><<<dim3(8, 256), 256, GS2>>>(nhi, w1T, b1, nullptr,
                                                  nullptr, hhi, D_, FFN_);
    gemm_mma<2, 2, 2><<<dim3(2, 256), 256, GS2>>>(hhi, w2T, b2, out,
                                                  out, nullptr, FFN_, D_);
}

// round 17
// speedup vs baseline: 1.0628x; 1.0628x over previous
#include <cuda_runtime.h>
#include <cuda_fp16.h>
#include <math.h>
#include <stdint.h>

#define B_   16
#define T_   1024
#define D_   512
#define H_   8
#define DH   64
#define FFN_ 2048
#define SEH  256
#define ROWS (B_*T_)   // 16384

// ---------------- scratch (static device allocations) ---------------------------
__device__ __align__(16) float g_y[ROWS];
__device__ __align__(16) float g_z1[B_*SEH];
__device__ __align__(16) float g_gate[ROWS];
__device__ __align__(16) __half g_qkvh[3*ROWS*D_];   // q(/8),k,v fp16
__device__ __align__(16) __half g_nhi[ROWS*D_];
__device__ __align__(16) __half g_hhi[ROWS*FFN_];
__device__ __align__(16) __half g_wqkvT[3*D_*D_];
__device__ __align__(16) __half g_w1T[FFN_*D_];
__device__ __align__(16) __half g_w2T[D_*FFN_];

// ---------------- helpers -------------------------------------------------------
#define SWZ(o) ((o) ^ (((o) >> 3) & 0x70))

__device__ __forceinline__ uint32_t smem_u32(const void* p) {
    uint32_t a;
    asm("{ .reg .u64 t; cvta.to.shared.u64 t, %1; cvt.u32.u64 %0, t; }" : "=r"(a) : "l"(p));
    return a;
}
__device__ __forceinline__ void cp16(uint32_t dst, const void* src) {
    asm volatile("cp.async.cg.shared.global [%0], [%1], 16;" :: "r"(dst), "l"(src) : "memory");
}
__device__ __forceinline__ void ldsm4(uint32_t* r, uint32_t a) {
    asm volatile("ldmatrix.sync.aligned.m8n8.x4.shared.b16 {%0,%1,%2,%3}, [%4];"
                 : "=r"(r[0]), "=r"(r[1]), "=r"(r[2]), "=r"(r[3]) : "r"(a));
}
__device__ __forceinline__ void ldsm4t(uint32_t* r, uint32_t a) {
    asm volatile("ldmatrix.sync.aligned.m8n8.x4.trans.shared.b16 {%0,%1,%2,%3}, [%4];"
                 : "=r"(r[0]), "=r"(r[1]), "=r"(r[2]), "=r"(r[3]) : "r"(a));
}
__device__ __forceinline__ void mma16816(float* d, const uint32_t* a, uint32_t b0, uint32_t b1) {
    asm volatile(
        "mma.sync.aligned.m16n8k16.row.col.f32.f16.f16.f32 "
        "{%0,%1,%2,%3}, {%4,%5,%6,%7}, {%8,%9}, {%0,%1,%2,%3};"
        : "+f"(d[0]), "+f"(d[1]), "+f"(d[2]), "+f"(d[3])
        : "r"(a[0]), "r"(a[1]), "r"(a[2]), "r"(a[3]), "r"(b0), "r"(b1));
}
__device__ __forceinline__ float gelu_f(float x) {
    return 0.5f * x * (1.0f + erff(x * 0.70710678118654752f));
}

// ---------------- row means (prologue) ------------------------------------------
__global__ __launch_bounds__(256) void rowmean_k(const float* __restrict__ x) {
    const int row  = blockIdx.x * 8 + (threadIdx.x >> 5);
    const int lane = threadIdx.x & 31;
    const float4* xr = (const float4*)(x + (size_t)row * D_);
    float s = 0.f;
#pragma unroll
    for (int i = 0; i < 4; i++) {
        float4 v = xr[lane + 32 * i];
        s += v.x + v.y + v.z + v.w;
    }
#pragma unroll
    for (int off = 16; off >= 1; off >>= 1) s += __shfl_xor_sync(0xffffffffu, s, off);
    if (lane == 0) g_y[row] = s * (1.f / D_);
}

// ---------------- fused SE fc1 + weight transposes ------------------------------
// blocks [0,256): se_fc1; blocks [256, 256+2816): weight transpose + fp32->fp16.
// Transpose CTAs fill the SMs while fc1 CTAs sit in load-latency stalls.
__global__ __launch_bounds__(256) void se_fc1_prep_k(
    const float* __restrict__ se_w1,
    const float* __restrict__ wq, const float* __restrict__ wk,
    const float* __restrict__ wv, const float* __restrict__ w1,
    const float* __restrict__ w2) {
    __shared__ float smf[1280];
    const int id = blockIdx.x;
    const int tid = threadIdx.x;
    if (id < 256) {
        float* ys = smf;
        float* ps = smf + 1024;
        const int b = id & 15, jt = id >> 4;
        for (int i = tid; i < T_; i += 256) ys[i] = g_y[b * T_ + i];
        __syncthreads();
        const int j = jt * 16 + (tid & 15);
        const int ks = tid >> 4;          // 0..15, each 64 k
        float acc = 0.f;
        const float* wp = se_w1 + (size_t)(ks * 64) * SEH + j;
        const float* yp = ys + ks * 64;
#pragma unroll 8
        for (int i = 0; i < 64; i++) acc += yp[i] * wp[(size_t)i * SEH];
        ps[tid] = acc;
        __syncthreads();
        if (tid < 16) {
            float s = ps[tid];
#pragma unroll
            for (int r = 1; r < 16; r++) s += ps[tid + r * 16];
            g_z1[b * SEH + jt * 16 + tid] = fmaxf(s, 0.f);
        }
        return;
    }
    float (*ts)[33] = (float(*)[33])smf;
    const int id2 = id - 256;
    const float* W;
    __half* Thi;
    int K, N, kb, nb;
    if (id2 < 768) {
        const int which = id2 >> 8, t = id2 & 255;
        W = (which == 0) ? wq : (which == 1) ? wk : wv;
        Thi = g_wqkvT + which * D_ * D_;
        K = D_; N = D_;
        nb = (t & 15) * 32; kb = (t >> 4) * 32;
    } else if (id2 < 1792) {
        const int t = id2 - 768;
        W = w1; Thi = g_w1T;
        K = D_; N = FFN_;
        nb = (t & 63) * 32; kb = (t >> 6) * 32;
    } else {
        const int t = id2 - 1792;
        W = w2; Thi = g_w2T;
        K = FFN_; N = D_;
        nb = (t & 15) * 32; kb = (t >> 4) * 32;
    }
    const int tx = tid & 31, ty = tid >> 5;
#pragma unroll
    for (int i = 0; i < 32; i += 8)
        ts[ty + i][tx] = W[(size_t)(kb + ty + i) * N + nb + tx];
    __syncthreads();
#pragma unroll
    for (int i = 0; i < 32; i += 8) {
        float v = ts[tx][ty + i];
        Thi[(size_t)(nb + ty + i) * K + kb + tx] = __float2half_rn(v);
    }
}

// ---------------- fused SE fc2 + gated LayerNorm -> fp16 ------------------------
__global__ __launch_bounds__(256) void se_fc2_ln_k(
    const float* __restrict__ w2, const float* __restrict__ x,
    const float* __restrict__ gw, const float* __restrict__ bw) {
    __shared__ float zs[SEH];
    __shared__ float ps[256];
    __shared__ float gs[64];
    const int b = blockIdx.x, tt = blockIdx.y;
    const int tid = threadIdx.x;
    if (tid < SEH) zs[tid] = g_z1[b * SEH + tid];
    __syncthreads();
    const int t = tt * 64 + (tid & 63);
    const int ks = tid >> 6;
    float acc = 0.f;
    const float* wp = w2 + (size_t)(ks * 64) * T_ + t;
    const float* zp = zs + ks * 64;
#pragma unroll 8
    for (int j = 0; j < 64; j++) acc += zp[j] * wp[(size_t)j * T_];
    ps[tid] = acc;
    __syncthreads();
    if (tid < 64) {
        float s = ps[tid] + ps[tid + 64] + ps[tid + 128] + ps[tid + 192];
        float g = 1.f / (1.f + __expf(-s));
        g_gate[b * T_ + tt * 64 + tid] = g;
        gs[tid] = g;
    }
    __syncthreads();

    const int wrp = tid >> 5, lane = tid & 31;
    for (int rr = wrp; rr < 64; rr += 8) {
        const int row = b * T_ + tt * 64 + rr;
        const float gm = 1.f + gs[rr];
        const float4* xr = (const float4*)(x + (size_t)row * D_);
        float4 r[4];
        float s = 0.f, s2 = 0.f;
#pragma unroll
        for (int i = 0; i < 4; i++) {
            float4 v = xr[lane + 32 * i];
            v.x *= gm; v.y *= gm; v.z *= gm; v.w *= gm;
            r[i] = v;
            s  += v.x + v.y + v.z + v.w;
            s2 += v.x * v.x + v.y * v.y + v.z * v.z + v.w * v.w;
        }
#pragma unroll
        for (int off = 16; off >= 1; off >>= 1) {
            s  += __shfl_xor_sync(0xffffffffu, s, off);
            s2 += __shfl_xor_sync(0xffffffffu, s2, off);
        }
        float mu = s * (1.f / D_);
        float rs = rsqrtf(s2 * (1.f / D_) - mu * mu + 1e-5f);
        const float4* g4 = (const float4*)gw;
        const float4* b4 = (const float4*)bw;
        uint2* hrow = (uint2*)(g_nhi + (size_t)row * D_);
#pragma unroll
        for (int i = 0; i < 4; i++) {
            int c = lane + 32 * i;
            float4 g = g4[c], bb = b4[c], v = r[i];
            v.x = (v.x - mu) * rs * g.x + bb.x;
            v.y = (v.y - mu) * rs * g.y + bb.y;
            v.z = (v.z - mu) * rs * g.z + bb.z;
            v.w = (v.w - mu) * rs * g.w + bb.w;
            __half2 h01 = __floats2half2_rn(v.x, v.y);
            __half2 h23 = __floats2half2_rn(v.z, v.w);
            uint2 hw;
            hw.x = *(uint32_t*)&h01; hw.y = *(uint32_t*)&h23;
            hrow[c] = hw;
        }
    }
}

// ---------------- plain LayerNorm -> fp16 (FFN pre-norm; 8 rows/CTA) -------------
__global__ __launch_bounds__(256) void ln_split_k(
    const float* __restrict__ x, const float* __restrict__ gw,
    const float* __restrict__ bw) {
    int row  = blockIdx.x * 8 + (threadIdx.x >> 5);
    int lane = threadIdx.x & 31;
    const float4* xr = (const float4*)(x + (size_t)row * D_);
    float4 r[4];
    float s = 0.f, s2 = 0.f;
#pragma unroll
    for (int i = 0; i < 4; i++) {
        float4 v = xr[lane + 32 * i];
        r[i] = v;
        s  += v.x + v.y + v.z + v.w;
        s2 += v.x * v.x + v.y * v.y + v.z * v.z + v.w * v.w;
    }
#pragma unroll
    for (int off = 16; off >= 1; off >>= 1) {
        s  += __shfl_xor_sync(0xffffffffu, s, off);
        s2 += __shfl_xor_sync(0xffffffffu, s2, off);
    }
    float mu = s * (1.f / D_);
    float rs = rsqrtf(s2 * (1.f / D_) - mu * mu + 1e-5f);
    const float4* g4 = (const float4*)gw;
    const float4* b4 = (const float4*)bw;
    uint2* hrow = (uint2*)(g_nhi + (size_t)row * D_);
#pragma unroll
    for (int i = 0; i < 4; i++) {
        int c = lane + 32 * i;
        float4 g = g4[c], bb = b4[c], v = r[i];
        v.x = (v.x - mu) * rs * g.x + bb.x;
        v.y = (v.y - mu) * rs * g.y + bb.y;
        v.z = (v.z - mu) * rs * g.z + bb.z;
        v.w = (v.w - mu) * rs * g.w + bb.w;
        __half2 h01 = __floats2half2_rn(v.x, v.y);
        __half2 h23 = __floats2half2_rn(v.z, v.w);
        uint2 hw;
        hw.x = *(uint32_t*)&h01; hw.y = *(uint32_t*)&h23;
        hrow[c] = hw;
    }
}

// ---------------- single-pass fp16 HMMA GEMM (64x256 tile, 2 CTAs/SM) -----------
// EPI: 0 = QKV -> fp16 split-by-512 buffers (q scaled 1/8)
//      1 = bias+GELU -> fp16,  2 = bias+res fp32
#define AM    64
#define MT    2
#define ATILE (AM*128)           // 8192
#define BTILE 32768              // 256 rows x 128B
#define GSTG  (ATILE + BTILE)    // 40KB
#define GSMEM (2*GSTG)           // 80KB

template <int EPI>
__global__ __launch_bounds__(256, 2)
void gemm_mma(const __half* __restrict__ Ahi, const __half* __restrict__ Bhi,
              const float* __restrict__ bias, const float* __restrict__ res,
              float* __restrict__ Cf, __half* __restrict__ Chi,
              int K, int ldc) {
    extern __shared__ char smem[];
    const uint32_t sbase = smem_u32(smem);
    const int tid = threadIdx.x;
    const int bm = blockIdx.y * AM, bn = blockIdx.x * 256;
    const int wid = tid >> 5, lane = tid & 31;
    const int wm = wid >> 2, wn = wid & 3;

    float acc[MT][8][4];
#pragma unroll
    for (int i = 0; i < MT; i++)
#pragma unroll
        for (int j = 0; j < 8; j++)
#pragma unroll
            for (int f = 0; f < 4; f++) acc[i][j][f] = 0.f;

    const int NC = K >> 6;
    const int lrow = (lane & 7) + ((lane >> 3) & 1) * 8;
    const int lch  = lane >> 4;

    uint32_t arow[MT], brow[4];
#pragma unroll
    for (int mt = 0; mt < MT; mt++) arow[mt] = (wm * 32 + mt * 16 + lrow) * 128;
#pragma unroll
    for (int nb = 0; nb < 4; nb++) brow[nb] = (wn * 64 + nb * 16 + lrow) * 128;

#define LOAD_CHUNK(c)                                                              \
    {                                                                              \
        const uint32_t stg = sbase + ((c) & 1) * GSTG;                             \
        const int kc = (c) << 6;                                                   \
        _Pragma("unroll")                                                          \
        for (int i = 0; i < MT; i++) {                                             \
            int slot = tid + i * 256;                                              \
            int r = slot >> 3, ch = slot & 7;                                      \
            cp16(stg + SWZ(r * 128 + ch * 16),                                     \
                 Ahi + (size_t)(bm + r) * K + kc + ch * 8);                        \
        }                                                                          \
        _Pragma("unroll")                                                          \
        for (int i = 0; i < 8; i++) {                                              \
            int slot = tid + i * 256;                                              \
            int r = slot >> 3, ch = slot & 7;                                      \
            cp16(stg + ATILE + SWZ(r * 128 + ch * 16),                             \
                 Bhi + (size_t)(bn + r) * K + kc + ch * 8);                        \
        }                                                                          \
        asm volatile("cp.async.commit_group;" ::: "memory");                       \
    }

    LOAD_CHUNK(0);
    for (int c = 0; c < NC; c++) {
        if (c + 1 < NC) {
            LOAD_CHUNK(c + 1);
            asm volatile("cp.async.wait_group 1;" ::: "memory");
        } else {
            asm volatile("cp.async.wait_group 0;" ::: "memory");
        }
        __syncthreads();
        const uint32_t stg = sbase + (c & 1) * GSTG;
#pragma unroll
        for (int k16 = 0; k16 < 4; k16++) {
            const uint32_t cb = (k16 * 2 + lch) * 16;
            uint32_t ah[MT][4], bh[4][4];
#pragma unroll
            for (int mt = 0; mt < MT; mt++) ldsm4(ah[mt], stg + SWZ(arow[mt] + cb));
#pragma unroll
            for (int nb = 0; nb < 4; nb++) ldsm4(bh[nb], stg + ATILE + SWZ(brow[nb] + cb));
#pragma unroll
            for (int mt = 0; mt < MT; mt++)
#pragma unroll
                for (int nb = 0; nb < 4; nb++)
#pragma unroll
                    for (int hf = 0; hf < 2; hf++)
                        mma16816(acc[mt][nb * 2 + hf], ah[mt], bh[nb][hf], bh[nb][hf + 2]);
        }
        __syncthreads();
    }

    const int er = bm + wm * 32 + (lane >> 2);
    const int ec = bn + wn * 64 + (lane & 3) * 2;
#pragma unroll
    for (int mt = 0; mt < MT; mt++)
#pragma unroll
        for (int rr = 0; rr < 2; rr++) {
            const int row = er + mt * 16 + rr * 8;
#pragma unroll
            for (int nf = 0; nf < 8; nf++) {
                const int col = ec + nf * 8;
                float v0 = acc[mt][nf][rr * 2 + 0];
                float v1 = acc[mt][nf][rr * 2 + 1];
                if (EPI == 0) {
                    const int buf = col >> 9;
                    const float sc = (buf == 0) ? 0.125f : 1.f;
                    v0 *= sc; v1 *= sc;
                    __half2 h = __floats2half2_rn(v0, v1);
                    size_t a = ((size_t)buf * ROWS + row) * 512 + (col & 511);
                    *(__half2*)(Chi + a) = h;
                } else if (EPI == 1) {
                    v0 = gelu_f(v0 + bias[col]);
                    v1 = gelu_f(v1 + bias[col + 1]);
                    __half2 h = __floats2half2_rn(v0, v1);
                    *(__half2*)(Chi + (size_t)row * ldc + col) = h;
                } else {
                    const float2 rr2 = *(const float2*)(res + (size_t)row * ldc + col);
                    float2 o = make_float2(v0 + bias[col] + rr2.x, v1 + bias[col + 1] + rr2.y);
                    *(float2*)(Cf + (size_t)row * ldc + col) = o;
                }
            }
        }
}

// ---------------- fp16 HMMA flash attention, max-free softmax -------------------
#define ASMEM (16384 + 2 * 16384)

__global__ __launch_bounds__(256, 2)
void attn_mma(const __half* __restrict__ qkvh,
              const float* __restrict__ x, float* __restrict__ out) {
    extern __shared__ char smem[];
    const uint32_t sbase = smem_u32(smem);
    const int b = blockIdx.z, h = blockIdx.y, qt = blockIdx.x;
    const int tid = threadIdx.x, w = tid >> 5, lane = tid & 31;
    const int bq = b * T_ + qt * 128;
    const int bk0 = b * T_;
    const int lrow = (lane & 7) + ((lane >> 3) & 1) * 8;
    const int lch  = lane >> 4;

    const __half* kh = qkvh + (size_t)ROWS * D_;
    const __half* vh = qkvh + 2 * (size_t)ROWS * D_;

    {
#pragma unroll
        for (int i = 0; i < 4; i++) {
            int slot = tid + i * 256;
            int r = slot >> 3, ch = slot & 7;
            cp16(sbase + SWZ(r * 128 + ch * 16),
                 qkvh + (size_t)(bq + r) * D_ + h * DH + ch * 8);
        }
    }
#define LOAD_KV(kt)                                                                \
    {                                                                              \
        const uint32_t stg = sbase + 16384 + ((kt) & 1) * 16384;                   \
        const int bk = bk0 + (kt) * 64;                                            \
        _Pragma("unroll")                                                          \
        for (int i = 0; i < 2; i++) {                                              \
            int slot = tid + i * 256;                                              \
            int r = slot >> 3, ch = slot & 7;                                      \
            cp16(stg + SWZ(r * 128 + ch * 16),                                     \
                 kh + (size_t)(bk + r) * D_ + h * DH + ch * 8);                    \
            cp16(stg + 8192 + SWZ(r * 128 + ch * 16),                              \
                 vh + (size_t)(bk + r) * D_ + h * DH + ch * 8);                    \
        }                                                                          \
        asm volatile("cp.async.commit_group;" ::: "memory");                       \
    }
    LOAD_KV(0);

    uint32_t qfh[4][4];
    float oacc[8][4];
#pragma unroll
    for (int t = 0; t < 8; t++)
#pragma unroll
        for (int f = 0; f < 4; f++) oacc[t][f] = 0.f;
    float l0 = 0.f, l1 = 0.f;

    for (int kt = 0; kt < 16; kt++) {
        if (kt + 1 < 16) {
            LOAD_KV(kt + 1);
            asm volatile("cp.async.wait_group 1;" ::: "memory");
        } else {
            asm volatile("cp.async.wait_group 0;" ::: "memory");
        }
        __syncthreads();

        if (kt == 0) {
#pragma unroll
            for (int j = 0; j < 4; j++)
                ldsm4(qfh[j], sbase + SWZ((w * 16 + lrow) * 128 + (j * 2 + lch) * 16));
        }
        const uint32_t stg = sbase + 16384 + (kt & 1) * 16384;

        // ---- S = Q K^T ----
        float sacc[8][4];
#pragma unroll
        for (int t = 0; t < 8; t++)
#pragma unroll
            for (int f = 0; f < 4; f++) sacc[t][f] = 0.f;
#pragma unroll
        for (int k16 = 0; k16 < 4; k16++) {
            const uint32_t cb = (k16 * 2 + lch) * 16;
            uint32_t bh[4][4];
#pragma unroll
            for (int g = 0; g < 4; g++)
                ldsm4(bh[g], stg + SWZ((g * 16 + lrow) * 128 + cb));
#pragma unroll
            for (int g = 0; g < 4; g++)
#pragma unroll
                for (int hf = 0; hf < 2; hf++)
                    mma16816(sacc[2 * g + hf], qfh[k16], bh[g][hf], bh[g][hf + 2]);
        }

        // ---- P = exp(S); per-thread l; convert to fragments ----
        uint32_t pa[4][4];
#pragma unroll
        for (int k16 = 0; k16 < 4; k16++)
#pragma unroll
            for (int half = 0; half < 2; half++) {
                const float* t0 = sacc[2 * k16 + half];
                float e0 = __expf(t0[0]);
                float e1 = __expf(t0[1]);
                float e2 = __expf(t0[2]);
                float e3 = __expf(t0[3]);
                l0 += e0 + e1;
                l1 += e2 + e3;
                __half2 h0 = __floats2half2_rn(e0, e1);
                __half2 h1 = __floats2half2_rn(e2, e3);
                pa[k16][2 * half + 0] = *(uint32_t*)&h0;
                pa[k16][2 * half + 1] = *(uint32_t*)&h1;
            }

        // ---- O += P V ----
        const uint32_t vs = stg + 8192;
        const int vr = (lane & 7) + ((lane >> 4) << 3);
        const int vb = ((lane >> 3) & 1) * 16;
#pragma unroll
        for (int k16 = 0; k16 < 4; k16++) {
#pragma unroll
            for (int nb = 0; nb < 4; nb++) {
                const uint32_t off = SWZ((k16 * 16 + vr) * 128 + nb * 32 + vb);
                uint32_t fvh[4];
                ldsm4t(fvh, vs + off);
#pragma unroll
                for (int hf = 0; hf < 2; hf++)
                    mma16816(oacc[2 * nb + hf], pa[k16], fvh[hf], fvh[hf + 2]);
            }
        }
        __syncthreads();
    }

    // ---- epilogue: row-sum reduce, then out = x*(1+gate) + O/l ----
    l0 += __shfl_xor_sync(0xffffffffu, l0, 1);
    l0 += __shfl_xor_sync(0xffffffffu, l0, 2);
    l1 += __shfl_xor_sync(0xffffffffu, l1, 1);
    l1 += __shfl_xor_sync(0xffffffffu, l1, 2);
    const float i0 = 1.f / l0, i1 = 1.f / l1;
    const int r0 = bq + w * 16 + (lane >> 2);
    const float gm0 = 1.f + g_gate[r0];
    const float gm1 = 1.f + g_gate[r0 + 8];
    const int cbase = h * DH + 2 * (lane & 3);
#pragma unroll
    for (int dt = 0; dt < 8; dt++) {
        const int col = cbase + dt * 8;
        const float2 x0 = *(const float2*)(x + (size_t)r0 * D_ + col);
        const float2 x1 = *(const float2*)(x + (size_t)(r0 + 8) * D_ + col);
        float2 o0 = make_float2(x0.x * gm0 + oacc[dt][0] * i0, x0.y * gm0 + oacc[dt][1] * i0);
        float2 o1 = make_float2(x1.x * gm1 + oacc[dt][2] * i1, x1.y * gm1 + oacc[dt][3] * i1);
        *(float2*)(out + (size_t)r0 * D_ + col) = o0;
        *(float2*)(out + (size_t)(r0 + 8) * D_ + col) = o1;
    }
}

// ---------------- launch --------------------------------------------------------
extern "C" void kernel_launch(void* const* d_in, const int* in_sizes, int n_in,
                              void* d_out, int out_size) {
    const float* x     = (const float*)d_in[0];
    const float* wq    = (const float*)d_in[1];
    const float* wk    = (const float*)d_in[2];
    const float* wv    = (const float*)d_in[3];
    const float* ln1_g = (const float*)d_in[4];
    const float* ln1_b = (const float*)d_in[5];
    const float* se_w1 = (const float*)d_in[6];
    const float* se_w2 = (const float*)d_in[7];
    const float* ffn_g = (const float*)d_in[8];
    const float* ffn_b = (const float*)d_in[9];
    const float* w1    = (const float*)d_in[10];
    const float* b1    = (const float*)d_in[11];
    const float* w2    = (const float*)d_in[12];
    const float* b2    = (const float*)d_in[13];
    float* out = (float*)d_out;

    __half *qkvh, *nhi, *hhi, *wqkvT, *w1T, *w2T;
    cudaGetSymbolAddress((void**)&qkvh,  g_qkvh);
    cudaGetSymbolAddress((void**)&nhi,   g_nhi);
    cudaGetSymbolAddress((void**)&hhi,   g_hhi);
    cudaGetSymbolAddress((void**)&wqkvT, g_wqkvT);
    cudaGetSymbolAddress((void**)&w1T,   g_w1T);
    cudaGetSymbolAddress((void**)&w2T,   g_w2T);

    cudaFuncSetAttribute(attn_mma, cudaFuncAttributeMaxDynamicSharedMemorySize, ASMEM);
    cudaFuncSetAttribute(gemm_mma<0>, cudaFuncAttributeMaxDynamicSharedMemorySize, GSMEM);
    cudaFuncSetAttribute(gemm_mma<1>, cudaFuncAttributeMaxDynamicSharedMemorySize, GSMEM);
    cudaFuncSetAttribute(gemm_mma<2>, cudaFuncAttributeMaxDynamicSharedMemorySize, GSMEM);

    rowmean_k<<<ROWS / 8, 256>>>(x);
    se_fc1_prep_k<<<256 + 2816, 256>>>(se_w1, wq, wk, wv, w1, w2);
    se_fc2_ln_k<<<dim3(B_, 16), 256>>>(se_w2, x, ln1_g, ln1_b);
    gemm_mma<0><<<dim3(6, 256), 256, GSMEM>>>(nhi, wqkvT, nullptr, nullptr,
                                              nullptr, qkvh, D_, 512);
    attn_mma<<<dim3(T_ / 128, H_, B_), 256, ASMEM>>>(qkvh, x, out);

    ln_split_k<<<ROWS / 8, 256>>>(out, ffn_g, ffn_b);
    gemm_mma<1><<<dim3(8, 256), 256, GSMEM>>>(nhi, w1T, b1, nullptr,
                                              nullptr, hhi, D_, FFN_);
    gemm_mma<2><<<dim3(2, 256), 256, GSMEM>>>(hhi, w2T, b2, out,
                                              out, nullptr, FFN_, D_);
}